// round 12
// baseline (speedup 1.0000x reference)
#include <cuda_runtime.h>
#include <cuda_fp16.h>
#include <cstdint>

// ConvLSTM2D via mma.sync fp16 + fp16x2 3-product split (rounds 7/10 base).
// Round 11: 2 CTAs/SM. CTA = 128 pixels x 128 gates (gate-permuted), 256 thr,
// 8 warps (2M x 4N, warp tile 64x32), 3-stage cp.async ring (32KB/stage).
// Gate permutation: new col b*128 + g*32 + fl  <->  old col g*64 + b*32 + fl,
// so each N-half CTA owns all 4 gates for 32 f-channels (fused epilogue kept).

#define kT    16
#define kNPix 32768
#define KX2   896        // x K-part: 9*96=864, padded to 896
#define KALL2 2624       // 896 + 9*192
#define NS_ALL 41
#define NS_X   14

// -------- device scratch (allocation-free rule) -----------------------------
__device__ __half g_xs[(size_t)8 * 16 * 4096 * 96];      // 100.7 MB
__device__ __half g_hs[2][(size_t)kNPix * 192];          // 2 x 12.6 MB
__device__ float  g_c [(size_t)kNPix * 64];              // 8.4 MB
__device__ __half g_Wb[(size_t)256 * KALL2];             // permuted cols
__device__ __align__(16) __half g_zeros[8];              // stays zero

// -------- helpers -----------------------------------------------------------
__device__ __forceinline__ uint32_t sm_u32(const void* p) {
    return (uint32_t)__cvta_generic_to_shared(p);
}
__device__ __forceinline__ uint32_t swz(uint32_t o) { return o ^ ((o >> 3) & 0x70); }

__device__ __forceinline__ void cp16(uint32_t dst, const void* src) {
    asm volatile("cp.async.cg.shared.global [%0], [%1], 16;"
                 :: "r"(dst), "l"(src));
}
__device__ __forceinline__ void cp_commit() {
    asm volatile("cp.async.commit_group;" ::: "memory");
}
__device__ __forceinline__ void cp_wait0() {
    asm volatile("cp.async.wait_group 0;" ::: "memory");
}
__device__ __forceinline__ void cp_wait1() {
    asm volatile("cp.async.wait_group 1;" ::: "memory");
}
__device__ __forceinline__ void ldsm4(uint32_t* r, uint32_t a) {
    asm volatile("ldmatrix.sync.aligned.m8n8.x4.shared.b16 {%0,%1,%2,%3}, [%4];"
                 : "=r"(r[0]), "=r"(r[1]), "=r"(r[2]), "=r"(r[3]) : "r"(a));
}
__device__ __forceinline__ void mma16816(float* c, const uint32_t* a,
                                         const uint32_t* b) {
    asm volatile(
        "mma.sync.aligned.m16n8k16.row.col.f32.f16.f16.f32 "
        "{%0,%1,%2,%3}, {%4,%5,%6,%7}, {%8,%9}, {%0,%1,%2,%3};"
        : "+f"(c[0]), "+f"(c[1]), "+f"(c[2]), "+f"(c[3])
        : "r"(a[0]), "r"(a[1]), "r"(a[2]), "r"(a[3]), "r"(b[0]), "r"(b[1]));
}
__device__ __forceinline__ float hsig(float v) {
    return fminf(fmaxf(v + 3.f, 0.f), 6.f) * (1.f / 6.f);
}

// -------- precompute: B' weights, interleaved K order + permuted gate cols ---
__global__ void wb_kernel(const float* __restrict__ W, const float* __restrict__ U)
{
    int k_all = blockIdx.x;      // 0..KALL2-1
    int n_new = threadIdx.x;     // 0..255 (permuted col)
    int blk  = n_new >> 7;
    int r    = n_new & 127;
    int gate = r >> 5;
    int fl   = r & 31;
    int n    = gate * 64 + blk * 32 + fl;   // original gate column

    float v = 0.f;
    int sub = 0;
    bool valid = false;
    if (k_all < KX2) {
        if (k_all < 864) {
            int tap = k_all / 96, rr = k_all % 96;
            sub = rr / 32;
            int cin = rr % 32;
            v = W[(size_t)(tap * 32 + cin) * 256 + n];
            valid = true;
        }
    } else {
        int k = k_all - KX2;
        int tap = k / 192, rr = k % 192;
        sub = rr / 64;
        int cin = rr % 64;
        v = U[(size_t)(tap * 64 + cin) * 256 + n];
        valid = true;
    }
    __half o = __float2half(0.f);
    if (valid) {
        __half hi = __float2half(v);
        o = (sub == 1) ? __float2half(v - __half2float(hi)) : hi;
    }
    g_Wb[(size_t)n_new * KALL2 + k_all] = o;
}

// -------- precompute: x split image ------------------------------------------
__global__ void xs_kernel(const float* __restrict__ x)
{
    size_t i = (size_t)blockIdx.x * blockDim.x + threadIdx.x;  // 16.7M
    int cin = (int)(i & 31);
    size_t p = i >> 5;
    float v = x[i];
    __half hi = __float2half(v);
    __half lo = __float2half(v - __half2float(hi));
    g_xs[p * 96 + cin]      = hi;
    g_xs[p * 96 + 32 + cin] = hi;
    g_xs[p * 96 + 64 + cin] = lo;
}

// -------- main step kernel ---------------------------------------------------
// Grid (256, 2): x = M tile (128 pixels), y = gate block (32 f-channels x 4 gates).
// 256 threads, 8 warps = 2(M) x 4(N), warp tile 64x32. Kc=64.
// 3-stage ring: stage st at st*32768: A 16KB, B 16KB.  Dyn smem 96KB/CTA.

__global__ __launch_bounds__(256, 2)
void lstm_step_kernel(const float* __restrict__ bias, float* __restrict__ out,
                      int t, int last)
{
    extern __shared__ __align__(16) char dsm_raw[];
    __shared__ float s_bias[128];

    const int tid = threadIdx.x;
    const int wid = tid >> 5;
    const int lane = tid & 31;
    const int m_tile = blockIdx.x * 128;
    const int blk = blockIdx.y;              // gate block: f channels blk*32..+31

    const uint32_t dyn = sm_u32(dsm_raw);
    const uint32_t base = (dyn + 1023) & ~1023u;
    char* dptr = dsm_raw + (base - dyn);

    if (tid < 128) {
        int gate = tid >> 5, fl = tid & 31;
        s_bias[tid] = bias[gate * 64 + blk * 32 + fl];
    }

    const int NS = (t == 0) ? NS_X : NS_ALL;
    const __half* h_rd = g_hs[t & 1];          // h_{t-1}
    __half*       h_wr = g_hs[(t & 1) ^ 1];    // h_t
    const __half* wb = g_Wb + (size_t)(blk * 128) * KALL2;

    auto load_slab = [&](int s, int buf) {
        const uint32_t abuf = base + (uint32_t)buf * 32768;
        const uint32_t bbuf = abuf + 16384;
        // A: 1024 16B chunks (128 rows x 8 kgroups), 4 per thread
#pragma unroll
        for (int i = 0; i < 4; i++) {
            int c = tid + i * 256;
            int m = c >> 3, kg = c & 7;
            int k0 = s * 64 + kg * 8;
            int p = m_tile + m;
            int bb = p >> 12, rem = p & 4095, py = rem >> 6, px = rem & 63;
            const __half* src = g_zeros;
            if (k0 < KX2) {
                if (k0 < 864) {
                    int tap = k0 / 96, ch = k0 % 96;   // ch multiple of 8
                    int y = py + tap / 3 - 1, xw = px + tap % 3 - 1;
                    if ((unsigned)y < 64u && (unsigned)xw < 64u)
                        src = g_xs + ((size_t)((bb * 16 + t) * 4096
                                               + (y << 6) + xw)) * 96 + ch;
                }
            } else {
                int k = k0 - KX2;
                int tap = k / 192, ch = k % 192;        // ch multiple of 8
                int y = py + tap / 3 - 1, xw = px + tap % 3 - 1;
                if ((unsigned)y < 64u && (unsigned)xw < 64u)
                    src = h_rd + ((size_t)((bb << 12) + (y << 6) + xw)) * 192 + ch;
            }
            cp16(abuf + swz((uint32_t)(m * 128 + kg * 16)), src);
        }
        // B: 1024 16B chunks (128 permuted gate rows x 8 kgroups), 4 per thread
#pragma unroll
        for (int i = 0; i < 4; i++) {
            int c = tid + i * 256;
            int n = c >> 3, kg = c & 7;
            cp16(bbuf + swz((uint32_t)(n * 128 + kg * 16)),
                 wb + (size_t)n * KALL2 + s * 64 + kg * 8);
        }
    };

    // accumulators: 4 m-subtiles x 4 n-subtiles x 4 f32  (warp tile 64x32)
    float cfr[4][4][4];
#pragma unroll
    for (int i = 0; i < 4; i++)
#pragma unroll
        for (int j = 0; j < 4; j++)
#pragma unroll
            for (int q = 0; q < 4; q++) cfr[i][j][q] = 0.f;

    const int wm0 = (wid >> 2) * 64;         // 0 or 64
    const int wn0 = (wid & 3) * 32;          // 0,32,64,96

    // 3-stage ring preamble
    load_slab(0, 0);
    cp_commit();
    load_slab(1, 1);
    cp_commit();

    int buf = 0;
    for (int s = 0; s < NS; s++) {
        if (s == NS - 1) cp_wait0(); else cp_wait1();
        __syncthreads();
        if (s + 2 < NS) {
            int nb = buf - 1; if (nb < 0) nb += 3;
            load_slab(s + 2, nb);
            cp_commit();
        }

        const uint32_t abuf = base + (uint32_t)buf * 32768;
        const uint32_t bbuf = abuf + 16384;
        const uint32_t arow = (uint32_t)((lane & 7) + ((lane >> 3) & 1) * 8);
        const uint32_t brow = (uint32_t)(wn0 + (lane & 7) + (lane >> 4) * 8);
#pragma unroll
        for (int ks = 0; ks < 4; ks++) {
            const uint32_t acol = (uint32_t)(ks * 16 + (lane >> 4) * 8) * 2;
            const uint32_t bcol = (uint32_t)(ks * 16 + ((lane >> 3) & 1) * 8) * 2;
            uint32_t af[4][4];
#pragma unroll
            for (int mi = 0; mi < 4; mi++)
                ldsm4(af[mi], abuf + swz((uint32_t)(wm0 + mi * 16 + arow) * 128 + acol));
            uint32_t b0[4], b1[4];
            ldsm4(b0, bbuf + swz(brow * 128 + bcol));
            ldsm4(b1, bbuf + swz((brow + 16) * 128 + bcol));
#pragma unroll
            for (int mi = 0; mi < 4; mi++) {
                mma16816(cfr[mi][0], af[mi], b0);
                mma16816(cfr[mi][1], af[mi], b0 + 2);
                mma16816(cfr[mi][2], af[mi], b1);
                mma16816(cfr[mi][3], af[mi], b1 + 2);
            }
        }
        if (++buf == 3) buf = 0;
    }
    __syncthreads();   // all mma done; smem free for staging

    // ---- fused LSTM epilogue: 128 pixels x 128 permuted gates --------------
    float* zbuf = (float*)dptr;                 // 128*128 f32 = 64KB

#pragma unroll
    for (int mi = 0; mi < 4; mi++) {
        int ml = wm0 + mi * 16 + (lane >> 2);
#pragma unroll
        for (int nj = 0; nj < 4; nj++) {
            int n = wn0 + nj * 8 + 2 * (lane & 3);
            *(float2*)(zbuf + ml * 128 + n) =
                make_float2(cfr[mi][nj][0], cfr[mi][nj][1]);
            *(float2*)(zbuf + (ml + 8) * 128 + n) =
                make_float2(cfr[mi][nj][2], cfr[mi][nj][3]);
        }
    }
    __syncthreads();

    {   // thread -> pixel p = tid>>1, 16 f-channels fl0..fl0+15
        const int p = tid >> 1;
        const int fl0 = (tid & 1) * 16;
        const int pix = m_tile + p;
        const int fg0 = blk * 32 + fl0;              // global f channel base
        const float* zr = zbuf + p * 128;

        float cp16v[16];
#pragma unroll
        for (int j = 0; j < 16; j += 4) *(float4*)&cp16v[j] = make_float4(0,0,0,0);
        if (t > 0) {
#pragma unroll
            for (int j = 0; j < 16; j += 4)
                *(float4*)&cp16v[j] = *(const float4*)(g_c + (size_t)pix * 64 + fg0 + j);
        }

        float cn16[16], hn16[16];
#pragma unroll
        for (int j = 0; j < 16; j++) {
            int fl = fl0 + j;
            float vi = zr[fl]       + s_bias[fl];
            float vf = zr[32 + fl]  + s_bias[32 + fl];
            float vc = zr[64 + fl]  + s_bias[64 + fl];
            float vo = zr[96 + fl]  + s_bias[96 + fl];
            float cn = hsig(vf) * cp16v[j] + hsig(vi) * fmaxf(vc, 0.f);
            cn16[j] = cn;
            hn16[j] = hsig(vo) * fmaxf(cn, 0.f);
        }
        if (last) {
#pragma unroll
            for (int j = 0; j < 16; j += 4)
                *(float4*)(out + (size_t)pix * 64 + fg0 + j) = *(float4*)&hn16[j];
        } else {
#pragma unroll
            for (int j = 0; j < 16; j += 4)
                *(float4*)(g_c + (size_t)pix * 64 + fg0 + j) = *(float4*)&cn16[j];
            uint32_t ph[8], pl[8];
#pragma unroll
            for (int j2 = 0; j2 < 8; j2++) {
                __half h0 = __float2half(hn16[2 * j2]);
                __half h1 = __float2half(hn16[2 * j2 + 1]);
                __half l0 = __float2half(hn16[2 * j2]     - __half2float(h0));
                __half l1 = __float2half(hn16[2 * j2 + 1] - __half2float(h1));
                ph[j2] = (uint32_t)__half_as_ushort(h0)
                       | ((uint32_t)__half_as_ushort(h1) << 16);
                pl[j2] = (uint32_t)__half_as_ushort(l0)
                       | ((uint32_t)__half_as_ushort(l1) << 16);
            }
            uint4 vh0 = make_uint4(ph[0], ph[1], ph[2], ph[3]);
            uint4 vh1 = make_uint4(ph[4], ph[5], ph[6], ph[7]);
            uint4 vl0 = make_uint4(pl[0], pl[1], pl[2], pl[3]);
            uint4 vl1 = make_uint4(pl[4], pl[5], pl[6], pl[7]);
            __half* hb = h_wr + (size_t)pix * 192 + fg0;
            *(uint4*)(hb)            = vh0;  *(uint4*)(hb + 8)        = vh1;
            *(uint4*)(hb + 64)       = vh0;  *(uint4*)(hb + 72)       = vh1;
            *(uint4*)(hb + 128)      = vl0;  *(uint4*)(hb + 136)      = vl1;
        }
    }
}

// ---------------------------------------------------------------------------

extern "C" void kernel_launch(void* const* d_in, const int* in_sizes, int n_in,
                              void* d_out, int out_size)
{
    const float* x    = (const float*)d_in[0];   // (8,16,64,64,32)
    const float* Wp   = (const float*)d_in[1];   // (3,3,32,256)
    const float* Up   = (const float*)d_in[2];   // (3,3,64,256)
    const float* bias = (const float*)d_in[3];   // (256,)
    float* out = (float*)d_out;                  // (8,64,64,64)

    cudaFuncSetAttribute(lstm_step_kernel,
                         cudaFuncAttributeMaxDynamicSharedMemorySize, 99328);

    wb_kernel<<<KALL2, 256>>>(Wp, Up);
    xs_kernel<<<65536, 256>>>(x);

    dim3 grid(256, 2);
    for (int t = 0; t < kT; t++)
        lstm_step_kernel<<<grid, 256, 99328>>>(bias, out, t, t == kT - 1 ? 1 : 0);
}

// round 15
// speedup vs baseline: 1.0518x; 1.0518x over previous
#include <cuda_runtime.h>
#include <cuda_fp16.h>
#include <cstdint>

// ConvLSTM2D via mma.sync fp16 + fp16x2 3-product split (round-10 base).
// Round 13: 1024-thread CTA, 32 warps (8/SMSP), warp tile 32x32 (32 accum
// regs -> 64 regs/thread cap) to overlap ldsm crossbar with tensor pipe.
// CTA = 128 pixels x 256 gates, Kc=64, 3-stage cp.async ring.

#define kT    16
#define kNPix 32768
#define KX2   896        // x K-part: 9*96=864, padded to 896
#define KALL2 2624       // 896 + 9*192
#define NS_ALL 41
#define NS_X   14

// -------- device scratch (allocation-free rule) -----------------------------
__device__ __half g_xs[(size_t)8 * 16 * 4096 * 96];      // 100.7 MB
__device__ __half g_hs[2][(size_t)kNPix * 192];          // 2 x 12.6 MB
__device__ float  g_c [(size_t)kNPix * 64];              // 8.4 MB
__device__ __half g_Wb[(size_t)256 * KALL2];             // 1.35 MB
__device__ __align__(16) __half g_zeros[8];              // stays zero

// -------- helpers -----------------------------------------------------------
__device__ __forceinline__ uint32_t sm_u32(const void* p) {
    return (uint32_t)__cvta_generic_to_shared(p);
}
__device__ __forceinline__ uint32_t swz(uint32_t o) { return o ^ ((o >> 3) & 0x70); }

__device__ __forceinline__ void cp16(uint32_t dst, const void* src) {
    asm volatile("cp.async.cg.shared.global [%0], [%1], 16;"
                 :: "r"(dst), "l"(src));
}
__device__ __forceinline__ void cp_commit() {
    asm volatile("cp.async.commit_group;" ::: "memory");
}
__device__ __forceinline__ void cp_wait0() {
    asm volatile("cp.async.wait_group 0;" ::: "memory");
}
__device__ __forceinline__ void cp_wait1() {
    asm volatile("cp.async.wait_group 1;" ::: "memory");
}
__device__ __forceinline__ void ldsm4(uint32_t* r, uint32_t a) {
    asm volatile("ldmatrix.sync.aligned.m8n8.x4.shared.b16 {%0,%1,%2,%3}, [%4];"
                 : "=r"(r[0]), "=r"(r[1]), "=r"(r[2]), "=r"(r[3]) : "r"(a));
}
__device__ __forceinline__ void mma16816(float* c, const uint32_t* a,
                                         const uint32_t* b) {
    asm volatile(
        "mma.sync.aligned.m16n8k16.row.col.f32.f16.f16.f32 "
        "{%0,%1,%2,%3}, {%4,%5,%6,%7}, {%8,%9}, {%0,%1,%2,%3};"
        : "+f"(c[0]), "+f"(c[1]), "+f"(c[2]), "+f"(c[3])
        : "r"(a[0]), "r"(a[1]), "r"(a[2]), "r"(a[3]), "r"(b[0]), "r"(b[1]));
}
__device__ __forceinline__ float hsig(float v) {
    return fminf(fmaxf(v + 3.f, 0.f), 6.f) * (1.f / 6.f);
}

// -------- precompute: B' weights in interleaved K order ----------------------
__global__ void wb_kernel(const float* __restrict__ W, const float* __restrict__ U)
{
    int k_all = blockIdx.x;      // 0..KALL2-1
    int n = threadIdx.x;         // 0..255
    float v = 0.f;
    int sub = 0;
    bool valid = false;
    if (k_all < KX2) {
        if (k_all < 864) {
            int tap = k_all / 96, r = k_all % 96;
            sub = r / 32;
            int cin = r % 32;
            v = W[(size_t)(tap * 32 + cin) * 256 + n];
            valid = true;
        }
    } else {
        int k = k_all - KX2;
        int tap = k / 192, r = k % 192;
        sub = r / 64;
        int cin = r % 64;
        v = U[(size_t)(tap * 64 + cin) * 256 + n];
        valid = true;
    }
    __half o = __float2half(0.f);
    if (valid) {
        __half hi = __float2half(v);
        o = (sub == 1) ? __float2half(v - __half2float(hi)) : hi;
    }
    g_Wb[(size_t)n * KALL2 + k_all] = o;
}

// -------- precompute: x split image ------------------------------------------
__global__ void xs_kernel(const float* __restrict__ x)
{
    size_t i = (size_t)blockIdx.x * blockDim.x + threadIdx.x;  // 16.7M
    int cin = (int)(i & 31);
    size_t p = i >> 5;
    float v = x[i];
    __half hi = __float2half(v);
    __half lo = __float2half(v - __half2float(hi));
    g_xs[p * 96 + cin]      = hi;
    g_xs[p * 96 + 32 + cin] = hi;
    g_xs[p * 96 + 64 + cin] = lo;
}

// -------- main step kernel ---------------------------------------------------
// 256 CTAs x 1024 threads; CTA = 128 pixels x 256 gates; 32 warps = 4(M)x8(N),
// warp tile 32x32. Kc=64. 3-stage ring: stage st at base+st*49152:
// A 16KB @+0, B 32KB @+16384.  144KB dynamic smem.

__global__ __launch_bounds__(1024, 1)
void lstm_step_kernel(const float* __restrict__ bias, float* __restrict__ out,
                      int t, int last)
{
    extern __shared__ __align__(16) char dsm_raw[];
    __shared__ float s_bias[256];

    const int tid = threadIdx.x;
    const int wid = tid >> 5;
    const int lane = tid & 31;
    const int m_tile = blockIdx.x * 128;

    const uint32_t dyn = sm_u32(dsm_raw);
    const uint32_t base = (dyn + 1023) & ~1023u;
    char* dptr = dsm_raw + (base - dyn);

    if (tid < 64) ((float4*)s_bias)[tid] = ((const float4*)bias)[tid];

    const int NS = (t == 0) ? NS_X : NS_ALL;
    const __half* h_rd = g_hs[t & 1];          // h_{t-1}
    __half*       h_wr = g_hs[(t & 1) ^ 1];    // h_t

    auto load_slab = [&](int s, int buf) {
        const uint32_t abuf = base + (uint32_t)buf * 49152;
        const uint32_t bbuf = abuf + 16384;
        // A: 1024 16B chunks (128 rows x 8 kgroups), 1 per thread
        {
            int m = tid >> 3, kg = tid & 7;
            int k0 = s * 64 + kg * 8;
            int p = m_tile + m;
            int bb = p >> 12, rem = p & 4095, py = rem >> 6, px = rem & 63;
            const __half* src = g_zeros;
            if (k0 < KX2) {
                if (k0 < 864) {
                    int tap = k0 / 96, ch = k0 % 96;   // ch multiple of 8
                    int y = py + tap / 3 - 1, xw = px + tap % 3 - 1;
                    if ((unsigned)y < 64u && (unsigned)xw < 64u)
                        src = g_xs + ((size_t)((bb * 16 + t) * 4096
                                               + (y << 6) + xw)) * 96 + ch;
                }
            } else {
                int k = k0 - KX2;
                int tap = k / 192, ch = k % 192;        // ch multiple of 8
                int y = py + tap / 3 - 1, xw = px + tap % 3 - 1;
                if ((unsigned)y < 64u && (unsigned)xw < 64u)
                    src = h_rd + ((size_t)((bb << 12) + (y << 6) + xw)) * 192 + ch;
            }
            cp16(abuf + swz((uint32_t)(m * 128 + kg * 16)), src);
        }
        // B: 2048 16B chunks (256 rows x 8 kgroups), 2 per thread
#pragma unroll
        for (int i = 0; i < 2; i++) {
            int c = tid + i * 1024;
            int n = c >> 3, kg = c & 7;
            cp16(bbuf + swz((uint32_t)(n * 128 + kg * 16)),
                 g_Wb + (size_t)n * KALL2 + s * 64 + kg * 8);
        }
    };

    // accumulators: 2 m-subtiles x 4 n-subtiles x 4 f32  (warp tile 32x32)
    float cfr[2][4][4];
#pragma unroll
    for (int i = 0; i < 2; i++)
#pragma unroll
        for (int j = 0; j < 4; j++)
#pragma unroll
            for (int q = 0; q < 4; q++) cfr[i][j][q] = 0.f;

    const int wm0 = (wid >> 3) * 32;         // 0,32,64,96
    const int wn0 = (wid & 7) * 32;          // 0..224 step 32

    // 3-stage ring preamble
    load_slab(0, 0);
    cp_commit();
    load_slab(1, 1);
    cp_commit();

    int buf = 0;
    for (int s = 0; s < NS; s++) {
        if (s == NS - 1) cp_wait0(); else cp_wait1();
        __syncthreads();
        if (s + 2 < NS) {
            int nb = buf - 1; if (nb < 0) nb += 3;
            load_slab(s + 2, nb);
            cp_commit();
        }

        const uint32_t abuf = base + (uint32_t)buf * 49152;
        const uint32_t bbuf = abuf + 16384;
        const uint32_t arow = (uint32_t)(wm0 + (lane & 7) + ((lane >> 3) & 1) * 8);
        const uint32_t brow = (uint32_t)(wn0 + (lane & 7) + (lane >> 4) * 8);
#pragma unroll
        for (int ks = 0; ks < 4; ks++) {
            const uint32_t acol = (uint32_t)(ks * 16 + (lane >> 4) * 8) * 2;
            const uint32_t bcol = (uint32_t)(ks * 16 + ((lane >> 3) & 1) * 8) * 2;
            uint32_t a0[4], a1[4], b0[4], b1[4];
            ldsm4(a0, abuf + swz(arow * 128 + acol));
            ldsm4(a1, abuf + swz((arow + 16) * 128 + acol));
            ldsm4(b0, bbuf + swz(brow * 128 + bcol));
            ldsm4(b1, bbuf + swz((brow + 16) * 128 + bcol));
            mma16816(cfr[0][0], a0, b0);
            mma16816(cfr[0][1], a0, b0 + 2);
            mma16816(cfr[0][2], a0, b1);
            mma16816(cfr[0][3], a0, b1 + 2);
            mma16816(cfr[1][0], a1, b0);
            mma16816(cfr[1][1], a1, b0 + 2);
            mma16816(cfr[1][2], a1, b1);
            mma16816(cfr[1][3], a1, b1 + 2);
        }
        if (++buf == 3) buf = 0;
    }
    __syncthreads();   // all mma done; smem buffers free for staging

    // ---- fused LSTM epilogue: two rounds of 64 pixels x 256 gates ----------
    float* zbuf = (float*)dptr;                 // 64*256 f32 = 64KB

    for (int r = 0; r < 2; r++) {
        if ((wm0 >> 6) == r) {
#pragma unroll
            for (int mi = 0; mi < 2; mi++) {
                int ml = (wm0 & 63) + mi * 16 + (lane >> 2);
#pragma unroll
                for (int nj = 0; nj < 4; nj++) {
                    int n = wn0 + nj * 8 + 2 * (lane & 3);
                    *(float2*)(zbuf + ml * 256 + n) =
                        make_float2(cfr[mi][nj][0], cfr[mi][nj][1]);
                    *(float2*)(zbuf + (ml + 8) * 256 + n) =
                        make_float2(cfr[mi][nj][2], cfr[mi][nj][3]);
                }
            }
        }
        __syncthreads();

        {   // gates: 64 pixels x 64 f; thread -> pixel p = tid>>4, 4 f values
            const int p = tid >> 4;
            const int f0 = (tid & 15) * 4;
            const int pix = m_tile + r * 64 + p;
            const float* zr = zbuf + p * 256;
            float cp4[4] = {0.f, 0.f, 0.f, 0.f};
            if (t > 0)
                *(float4*)cp4 = *(const float4*)(g_c + (size_t)pix * 64 + f0);
            float cn4[4], hn4[4];
#pragma unroll
            for (int j = 0; j < 4; j++) {
                int f = f0 + j;
                float vi = zr[f]       + s_bias[f];
                float vf = zr[64 + f]  + s_bias[64 + f];
                float vc = zr[128 + f] + s_bias[128 + f];
                float vo = zr[192 + f] + s_bias[192 + f];
                float cn = hsig(vf) * cp4[j] + hsig(vi) * fmaxf(vc, 0.f);
                cn4[j] = cn;
                hn4[j] = hsig(vo) * fmaxf(cn, 0.f);
            }
            if (last) {
                *(float4*)(out + (size_t)pix * 64 + f0) = *(float4*)hn4;
            } else {
                *(float4*)(g_c + (size_t)pix * 64 + f0) = *(float4*)cn4;
                uint32_t ph[2], pl[2];
#pragma unroll
                for (int j2 = 0; j2 < 2; j2++) {
                    __half h0 = __float2half(hn4[2 * j2]);
                    __half h1 = __float2half(hn4[2 * j2 + 1]);
                    __half l0 = __float2half(hn4[2 * j2]     - __half2float(h0));
                    __half l1 = __float2half(hn4[2 * j2 + 1] - __half2float(h1));
                    ph[j2] = (uint32_t)__half_as_ushort(h0)
                           | ((uint32_t)__half_as_ushort(h1) << 16);
                    pl[j2] = (uint32_t)__half_as_ushort(l0)
                           | ((uint32_t)__half_as_ushort(l1) << 16);
                }
                uint2 vh = make_uint2(ph[0], ph[1]);
                uint2 vl = make_uint2(pl[0], pl[1]);
                __half* hb = h_wr + (size_t)pix * 192 + f0;
                *(uint2*)(hb)       = vh;
                *(uint2*)(hb + 64)  = vh;
                *(uint2*)(hb + 128) = vl;
            }
        }
        __syncthreads();
    }
}

// ---------------------------------------------------------------------------

extern "C" void kernel_launch(void* const* d_in, const int* in_sizes, int n_in,
                              void* d_out, int out_size)
{
    const float* x    = (const float*)d_in[0];   // (8,16,64,64,32)
    const float* Wp   = (const float*)d_in[1];   // (3,3,32,256)
    const float* Up   = (const float*)d_in[2];   // (3,3,64,256)
    const float* bias = (const float*)d_in[3];   // (256,)
    float* out = (float*)d_out;                  // (8,64,64,64)

    cudaFuncSetAttribute(lstm_step_kernel,
                         cudaFuncAttributeMaxDynamicSharedMemorySize, 148480);

    wb_kernel<<<KALL2, 256>>>(Wp, Up);
    xs_kernel<<<65536, 256>>>(x);

    for (int t = 0; t < kT; t++)
        lstm_step_kernel<<<256, 1024, 148480>>>(bias, out, t, t == kT - 1 ? 1 : 0);
}